// round 3
// baseline (speedup 1.0000x reference)
#include <cuda_runtime.h>
#include <math.h>

#define BB   64
#define DECL 12
#define FF   32
#define HH   512
#define EE   96
#define TT   4
#define G3   1536
#define NPRE 3584   /* 512 (query) + 1536 (gh0) + 1536 (gh1) */
#define KX0  544    /* F + H */
#define KOUT 1056   /* 2H + F */

// ---------------- device scratch (no allocations allowed) ----------------
__device__ __align__(16) float g_encproj[BB*EE*HH];   // 12.6 MB
__device__ __align__(16) float g_h0[BB*HH];
__device__ __align__(16) float g_h1[BB*HH];
__device__ __align__(16) float g_cur[BB*FF];
__device__ __align__(16) float g_pre[4][BB*NPRE];     // K-split partials: query|gh0|gh1
__device__ __align__(16) float g_gi[4][BB*G3];        // K-split partials for gi (layer0/1 reuse)
__device__ __align__(16) float g_x0[BB*KX0];          // [cur | ws]
__device__ __align__(16) float g_ws[BB*HH];

// ---------------- math helpers ----------------
__device__ __forceinline__ float fast_sigmoid(float x) {
    return 1.0f / (1.0f + __expf(-x));
}
__device__ __forceinline__ float fast_tanh(float x) {
    float e = __expf(-2.0f * fabsf(x));
    float t = (1.0f - e) / (1.0f + e);
    return copysignf(t, x);
}

// ---------------- generic 64x64 fp32 GEMM tile ----------------
// C[64][64] (row stride ldc) = A[64][klen] (row stride lda) @ W[64][klen]^T (row stride ldw)
// A,W,C pointers already offset to the tile origin. klen % 32 == 0.
__device__ __forceinline__ void gemm_tile(
    const float* __restrict__ A, int lda,
    const float* __restrict__ W, int ldw,
    float* __restrict__ C, int ldc, int klen)
{
    __shared__ float As[64][34];
    __shared__ float Ws[64][34];
    const int tid = threadIdx.x;          // 256 threads
    const int tx = tid & 15;              // column group
    const int ty = tid >> 4;              // row group
    float acc[4][4] = {};

    for (int k0 = 0; k0 < klen; k0 += 32) {
        // stage A and W chunks: 64 rows x 32 floats each = 512 float4 per array
        #pragma unroll
        for (int ph = 0; ph < 2; ph++) {
            int t   = tid + ph * 256;
            int row = t >> 3;
            int q   = (t & 7) << 2;
            float4 va = *reinterpret_cast<const float4*>(&A[row * lda + k0 + q]);
            As[row][q+0] = va.x; As[row][q+1] = va.y;
            As[row][q+2] = va.z; As[row][q+3] = va.w;
            float4 vw = *reinterpret_cast<const float4*>(&W[row * ldw + k0 + q]);
            Ws[row][q+0] = vw.x; Ws[row][q+1] = vw.y;
            Ws[row][q+2] = vw.z; Ws[row][q+3] = vw.w;
        }
        __syncthreads();

        #pragma unroll
        for (int kk = 0; kk < 32; kk++) {
            float a0 = As[ty     ][kk];
            float a1 = As[ty + 16][kk];
            float a2 = As[ty + 32][kk];
            float a3 = As[ty + 48][kk];
            float w0 = Ws[tx     ][kk];
            float w1 = Ws[tx + 16][kk];
            float w2 = Ws[tx + 32][kk];
            float w3 = Ws[tx + 48][kk];
            acc[0][0] += a0*w0; acc[0][1] += a0*w1; acc[0][2] += a0*w2; acc[0][3] += a0*w3;
            acc[1][0] += a1*w0; acc[1][1] += a1*w1; acc[1][2] += a1*w2; acc[1][3] += a1*w3;
            acc[2][0] += a2*w0; acc[2][1] += a2*w1; acc[2][2] += a2*w2; acc[2][3] += a2*w3;
            acc[3][0] += a3*w0; acc[3][1] += a3*w1; acc[3][2] += a3*w2; acc[3][3] += a3*w3;
        }
        __syncthreads();
    }

    #pragma unroll
    for (int i = 0; i < 4; i++)
        #pragma unroll
        for (int j = 0; j < 4; j++)
            C[(ty + 16*i) * ldc + tx + 16*j] = acc[i][j];
}

// ---------------- kernels ----------------

// copy initial hidden state and cur = inputs[:, 0, :]
__global__ void k_init(const float* __restrict__ hidden, const float* __restrict__ inputs) {
    int i = blockIdx.x * blockDim.x + threadIdx.x;
    if (i < BB * HH) {
        g_h0[i] = hidden[i];
        g_h1[i] = hidden[BB*HH + i];
    }
    if (i < BB * FF) {
        int b = i >> 5, f = i & 31;
        g_cur[i] = inputs[b * DECL * FF + f];
    }
}

// enc_proj[b*E+e][g] = sum_h enc[b,e,h] * W_attn[g][512+h]
__global__ __launch_bounds__(256) void k_encproj(
    const float* __restrict__ enc, const float* __restrict__ Wattn)
{
    int col0 = blockIdx.x * 64;   // g tile (N = 512 -> 8)
    int row0 = blockIdx.y * 64;   // (b,e) tile (M = 6144 -> 96)
    gemm_tile(enc + row0 * HH, HH,
              Wattn + col0 * (2*HH) + HH, 2*HH,
              g_encproj + row0 * HH + col0, HH, HH);
}

// pre: query = h1 @ Wa_h^T ; gh0 = h0 @ Wh0^T ; gh1 = h1 @ Wh1^T   (K split into 4x128)
__global__ __launch_bounds__(256) void k_pre(
    const float* __restrict__ Wattn, const float* __restrict__ Wh0,
    const float* __restrict__ Wh1)
{
    int col0 = blockIdx.x * 64;   // 0..55
    int s    = blockIdx.y;        // 0..3
    int k0   = s * 128;
    const float* A; const float* W; int ldw;
    if (col0 < 512)        { A = g_h1; W = Wattn + col0 * (2*HH);      ldw = 2*HH; }
    else if (col0 < 2048)  { A = g_h0; W = Wh0 + (col0 - 512) * HH;    ldw = HH;   }
    else                   { A = g_h1; W = Wh1 + (col0 - 2048) * HH;   ldw = HH;   }
    gemm_tile(A + k0, HH, W + k0, ldw, g_pre[s] + col0, NPRE, 128);
}

// attention: scores -> softmax -> ws ; also assembles g_x0 = [cur | ws]
__global__ __launch_bounds__(512) void k_attn(
    const float* __restrict__ enc, const float* __restrict__ b_attn,
    const float* __restrict__ v_attn)
{
    __shared__ float qs[HH];
    __shared__ float vs[HH];
    __shared__ float sc[EE];
    const int b = blockIdx.x;
    const int tid = threadIdx.x;     // 512
    const int warp = tid >> 5, lane = tid & 31;

    float q = b_attn[tid];
    #pragma unroll
    for (int s = 0; s < 4; s++) q += g_pre[s][b*NPRE + tid];
    qs[tid] = q;
    vs[tid] = v_attn[tid];
    __syncthreads();

    // scores: 16 warps x 6 energies each
    for (int e = warp; e < EE; e += 16) {
        const float* ep = g_encproj + (b*EE + e) * HH;
        float ssum = 0.0f;
        #pragma unroll 4
        for (int g = lane; g < HH; g += 32)
            ssum += fast_tanh(ep[g] + qs[g]) * vs[g];
        #pragma unroll
        for (int off = 16; off > 0; off >>= 1)
            ssum += __shfl_xor_sync(0xffffffffu, ssum, off);
        if (lane == 0) sc[e] = ssum;
    }
    __syncthreads();

    // softmax over E=96 (3 per lane, warp 0)
    if (warp == 0) {
        float s0 = sc[lane], s1 = sc[lane+32], s2 = sc[lane+64];
        float m = fmaxf(s0, fmaxf(s1, s2));
        #pragma unroll
        for (int off = 16; off > 0; off >>= 1)
            m = fmaxf(m, __shfl_xor_sync(0xffffffffu, m, off));
        float p0 = __expf(s0 - m), p1 = __expf(s1 - m), p2 = __expf(s2 - m);
        float sum = p0 + p1 + p2;
        #pragma unroll
        for (int off = 16; off > 0; off >>= 1)
            sum += __shfl_xor_sync(0xffffffffu, sum, off);
        float inv = 1.0f / sum;
        sc[lane]    = p0 * inv;
        sc[lane+32] = p1 * inv;
        sc[lane+64] = p2 * inv;
    }
    __syncthreads();

    // ws[b][h] = sum_e w_e * enc[b,e,h]
    float acc = 0.0f;
    const float* eb = enc + b*EE*HH + tid;
    #pragma unroll 4
    for (int e = 0; e < EE; e++) acc += sc[e] * eb[e*HH];
    g_ws[b*HH + tid] = acc;
    g_x0[b*KX0 + FF + tid] = acc;
    if (tid < FF) g_x0[b*KX0 + tid] = g_cur[b*FF + tid];
}

// gi0 = x0 @ Wi0^T  (K=544 split {160,128,128,128})
__global__ __launch_bounds__(256) void k_gi0(const float* __restrict__ Wi0) {
    const int k0s[4] = {0, 160, 288, 416};
    const int kls[4] = {160, 128, 128, 128};
    int col0 = blockIdx.x * 64;  // 0..23
    int s = blockIdx.y;
    gemm_tile(g_x0 + k0s[s], KX0,
              Wi0 + col0 * KX0 + k0s[s], KX0,
              g_gi[s] + col0, G3, kls[s]);
}

// gi1 = h0_new @ Wi1^T  (K=512 split 4x128)
__global__ __launch_bounds__(256) void k_gi1(const float* __restrict__ Wi1) {
    int col0 = blockIdx.x * 64;
    int s = blockIdx.y;
    int k0 = s * 128;
    gemm_tile(g_h0 + k0, HH,
              Wi1 + col0 * HH + k0, HH,
              g_gi[s] + col0, G3, 128);
}

// GRU combine: sums K-split partials, applies gates, updates hidden in place
__global__ __launch_bounds__(512) void k_comb(
    const float* __restrict__ bi, const float* __restrict__ bh,
    int ghoff, float* __restrict__ hbuf)
{
    const int b = blockIdx.x;
    const int j = threadIdx.x;
    float ir = bi[j], iz = bi[j+HH], in_ = bi[j+2*HH];
    float hr = bh[j], hz = bh[j+HH], hn  = bh[j+2*HH];
    #pragma unroll
    for (int s = 0; s < 4; s++) {
        const float* gi = g_gi[s] + b*G3;
        ir  += gi[j]; iz += gi[j+HH]; in_ += gi[j+2*HH];
        const float* gh = g_pre[s] + b*NPRE + ghoff;
        hr  += gh[j]; hz += gh[j+HH]; hn  += gh[j+2*HH];
    }
    float r = fast_sigmoid(ir + hr);
    float z = fast_sigmoid(iz + hz);
    float n = fast_tanh(in_ + r * hn);
    float hp = hbuf[b*HH + j];
    hbuf[b*HH + j] = (1.0f - z) * n + z * hp;
}

// output projection + writes d_out + prepares next-step cur
__global__ __launch_bounds__(128) void k_out(
    const float* __restrict__ W_out, const float* __restrict__ b_out,
    const float* __restrict__ inputs, const int* __restrict__ tindices,
    float* __restrict__ dout, int tstep)
{
    const int b = blockIdx.x;
    const int tid = threadIdx.x;   // 128
    const int warp = tid >> 5, lane = tid & 31;
    float a0 = 0.f, a1 = 0.f, a2 = 0.f, a3 = 0.f;
    for (int k = tid; k < KOUT; k += 128) {
        float x;
        if (k < HH)            x = g_h1[b*HH + k];
        else if (k < 2*HH)     x = g_ws[b*HH + k - HH];
        else                   x = g_cur[b*FF + (k - 2*HH)];
        a0 += x * W_out[k];
        a1 += x * W_out[KOUT + k];
        a2 += x * W_out[2*KOUT + k];
        a3 += x * W_out[3*KOUT + k];
    }
    #pragma unroll
    for (int off = 16; off > 0; off >>= 1) {
        a0 += __shfl_xor_sync(0xffffffffu, a0, off);
        a1 += __shfl_xor_sync(0xffffffffu, a1, off);
        a2 += __shfl_xor_sync(0xffffffffu, a2, off);
        a3 += __shfl_xor_sync(0xffffffffu, a3, off);
    }
    __shared__ float red[4][4];
    __shared__ float y[4];
    if (lane == 0) { red[0][warp] = a0; red[1][warp] = a1; red[2][warp] = a2; red[3][warp] = a3; }
    __syncthreads();
    if (tid < 4) {
        float s = red[tid][0] + red[tid][1] + red[tid][2] + red[tid][3] + b_out[tid];
        y[tid] = s;
        dout[(b*DECL + tstep)*TT + tid] = s;
    }
    __syncthreads();
    // next cur = inputs[:, tstep, :] with cur[:, target_indices] = out
    if (tid < FF) g_cur[b*FF + tid] = inputs[(b*DECL + tstep)*FF + tid];
    __syncthreads();
    if (tid < TT) g_cur[b*FF + tindices[tid]] = y[tid];
}

// ---------------- launch ----------------
extern "C" void kernel_launch(void* const* d_in, const int* in_sizes, int n_in,
                              void* d_out, int out_size)
{
    const float* inputs   = (const float*)d_in[0];
    const float* hidden   = (const float*)d_in[1];
    const float* enc      = (const float*)d_in[2];
    const int*   tindices = (const int*)  d_in[3];
    const float* W_attn   = (const float*)d_in[4];
    const float* b_attn   = (const float*)d_in[5];
    const float* v_attn   = (const float*)d_in[6];
    const float* Wi0      = (const float*)d_in[7];
    const float* Wh0      = (const float*)d_in[8];
    const float* bi0      = (const float*)d_in[9];
    const float* bh0      = (const float*)d_in[10];
    const float* Wi1      = (const float*)d_in[11];
    const float* Wh1      = (const float*)d_in[12];
    const float* bi1      = (const float*)d_in[13];
    const float* bh1      = (const float*)d_in[14];
    const float* W_out    = (const float*)d_in[15];
    const float* b_out    = (const float*)d_in[16];
    float* out = (float*)d_out;

    k_init<<<128, 256>>>(hidden, inputs);
    k_encproj<<<dim3(8, 96), 256>>>(enc, W_attn);

    float* g_h0p; float* g_h1p;
    cudaGetSymbolAddress((void**)&g_h0p, g_h0);
    cudaGetSymbolAddress((void**)&g_h1p, g_h1);

    for (int t = 0; t < DECL; t++) {
        k_pre <<<dim3(56, 4), 256>>>(W_attn, Wh0, Wh1);
        k_attn<<<64, 512>>>(enc, b_attn, v_attn);
        k_gi0 <<<dim3(24, 4), 256>>>(Wi0);
        k_comb<<<64, 512>>>(bi0, bh0, 512,  g_h0p);
        k_gi1 <<<dim3(24, 4), 256>>>(Wi1);
        k_comb<<<64, 512>>>(bi1, bh1, 2048, g_h1p);
        k_out <<<64, 128>>>(W_out, b_out, inputs, tindices, out, t);
    }
}

// round 4
// speedup vs baseline: 1.3036x; 1.3036x over previous
#include <cuda_runtime.h>
#include <math.h>

#define BB   64
#define DECL 12
#define FF   32
#define HH   512
#define EE   96
#define TT   4
#define G3   1536
#define NPRE 3584   /* 512 (query) + 1536 (gh0) + 1536 (gh1) */
#define KX0  544    /* F + H */
#define KOUT 1056   /* 2H + F */

// ---------------- device scratch (no allocations allowed) ----------------
__device__ __align__(16) float g_encproj[BB*EE*HH];   // 12.6 MB
__device__ __align__(16) float g_h0[BB*HH];
__device__ __align__(16) float g_h1[BB*HH];
__device__ __align__(16) float g_cur[BB*FF];
__device__ __align__(16) float g_pre[4][BB*NPRE];     // K-split partials: query|gh0|gh1
__device__ __align__(16) float g_gi[4][BB*G3];        // K-split partials for gi (layer0/1 reuse)
__device__ __align__(16) float g_x0[BB*KX0];          // [cur | ws]
__device__ __align__(16) float g_ws[BB*HH];
__device__ __align__(16) float g_sc[BB*EE];           // attention scores

// ---------------- math helpers ----------------
__device__ __forceinline__ float fast_sigmoid(float x) {
    return 1.0f / (1.0f + __expf(-x));
}
__device__ __forceinline__ float fast_tanh(float x) {
    float e = __expf(-2.0f * fabsf(x));
    float t = (1.0f - e) / (1.0f + e);
    return copysignf(t, x);
}

// ---------------- generic 64x64 fp32 GEMM tile ----------------
__device__ __forceinline__ void gemm_tile(
    const float* __restrict__ A, int lda,
    const float* __restrict__ W, int ldw,
    float* __restrict__ C, int ldc, int klen)
{
    __shared__ float As[64][34];
    __shared__ float Ws[64][34];
    const int tid = threadIdx.x;          // 256 threads
    const int tx = tid & 15;              // column group
    const int ty = tid >> 4;              // row group
    float acc[4][4] = {};

    for (int k0 = 0; k0 < klen; k0 += 32) {
        #pragma unroll
        for (int ph = 0; ph < 2; ph++) {
            int t   = tid + ph * 256;
            int row = t >> 3;
            int q   = (t & 7) << 2;
            float4 va = *reinterpret_cast<const float4*>(&A[row * lda + k0 + q]);
            As[row][q+0] = va.x; As[row][q+1] = va.y;
            As[row][q+2] = va.z; As[row][q+3] = va.w;
            float4 vw = *reinterpret_cast<const float4*>(&W[row * ldw + k0 + q]);
            Ws[row][q+0] = vw.x; Ws[row][q+1] = vw.y;
            Ws[row][q+2] = vw.z; Ws[row][q+3] = vw.w;
        }
        __syncthreads();

        #pragma unroll
        for (int kk = 0; kk < 32; kk++) {
            float a0 = As[ty     ][kk];
            float a1 = As[ty + 16][kk];
            float a2 = As[ty + 32][kk];
            float a3 = As[ty + 48][kk];
            float w0 = Ws[tx     ][kk];
            float w1 = Ws[tx + 16][kk];
            float w2 = Ws[tx + 32][kk];
            float w3 = Ws[tx + 48][kk];
            acc[0][0] += a0*w0; acc[0][1] += a0*w1; acc[0][2] += a0*w2; acc[0][3] += a0*w3;
            acc[1][0] += a1*w0; acc[1][1] += a1*w1; acc[1][2] += a1*w2; acc[1][3] += a1*w3;
            acc[2][0] += a2*w0; acc[2][1] += a2*w1; acc[2][2] += a2*w2; acc[2][3] += a2*w3;
            acc[3][0] += a3*w0; acc[3][1] += a3*w1; acc[3][2] += a3*w2; acc[3][3] += a3*w3;
        }
        __syncthreads();
    }

    #pragma unroll
    for (int i = 0; i < 4; i++)
        #pragma unroll
        for (int j = 0; j < 4; j++)
            C[(ty + 16*i) * ldc + tx + 16*j] = acc[i][j];
}

// ---------------- kernels ----------------

__global__ void k_init(const float* __restrict__ hidden, const float* __restrict__ inputs) {
    int i = blockIdx.x * blockDim.x + threadIdx.x;
    if (i < BB * HH) {
        g_h0[i] = hidden[i];
        g_h1[i] = hidden[BB*HH + i];
    }
    if (i < BB * FF) {
        int b = i >> 5, f = i & 31;
        g_cur[i] = inputs[b * DECL * FF + f];
    }
}

__global__ __launch_bounds__(256) void k_encproj(
    const float* __restrict__ enc, const float* __restrict__ Wattn)
{
    int col0 = blockIdx.x * 64;
    int row0 = blockIdx.y * 64;
    gemm_tile(enc + row0 * HH, HH,
              Wattn + col0 * (2*HH) + HH, 2*HH,
              g_encproj + row0 * HH + col0, HH, HH);
}

// pre: query = h1 @ Wa_h^T ; gh0 = h0 @ Wh0^T ; gh1 = h1 @ Wh1^T   (K split into 4x128)
__global__ __launch_bounds__(256) void k_pre(
    const float* __restrict__ Wattn, const float* __restrict__ Wh0,
    const float* __restrict__ Wh1)
{
    int col0 = blockIdx.x * 64;   // 0..55
    int s    = blockIdx.y;        // 0..3
    int k0   = s * 128;
    const float* A; const float* W; int ldw;
    if (col0 < 512)        { A = g_h1; W = Wattn + col0 * (2*HH);      ldw = 2*HH; }
    else if (col0 < 2048)  { A = g_h0; W = Wh0 + (col0 - 512) * HH;    ldw = HH;   }
    else                   { A = g_h1; W = Wh1 + (col0 - 2048) * HH;   ldw = HH;   }
    gemm_tile(A + k0, HH, W + k0, ldw, g_pre[s] + col0, NPRE, 128);
}

// scores: one warp per (b,e); grid = B*6 blocks of 512 threads (16 warps = 16 energies)
__global__ __launch_bounds__(512) void k_score(
    const float* __restrict__ b_attn, const float* __restrict__ v_attn)
{
    __shared__ float qs[HH];
    __shared__ float vs[HH];
    const int b    = blockIdx.x / 6;
    const int part = blockIdx.x % 6;
    const int tid  = threadIdx.x;
    const int warp = tid >> 5, lane = tid & 31;

    // build query vector (redundant per part, 10 KB of L2 reads per block)
    float q = b_attn[tid];
    #pragma unroll
    for (int s = 0; s < 4; s++) q += g_pre[s][b*NPRE + tid];
    qs[tid] = q;
    vs[tid] = v_attn[tid];
    __syncthreads();

    const int e = part * 16 + warp;
    const float4* ep4 = reinterpret_cast<const float4*>(g_encproj + (b*EE + e) * HH);
    float ssum = 0.0f;
    #pragma unroll
    for (int i = 0; i < 4; i++) {
        float4 v = ep4[i*32 + lane];
        int g = (i*32 + lane) * 4;
        ssum += fast_tanh(v.x + qs[g  ]) * vs[g  ];
        ssum += fast_tanh(v.y + qs[g+1]) * vs[g+1];
        ssum += fast_tanh(v.z + qs[g+2]) * vs[g+2];
        ssum += fast_tanh(v.w + qs[g+3]) * vs[g+3];
    }
    #pragma unroll
    for (int off = 16; off > 0; off >>= 1)
        ssum += __shfl_xor_sync(0xffffffffu, ssum, off);
    if (lane == 0) g_sc[b*EE + e] = ssum;
}

// softmax over E, weighted sum ws, assemble x0 = [cur | ws]
__global__ __launch_bounds__(512) void k_softmax_ws(const float* __restrict__ enc)
{
    __shared__ float sc[EE];
    const int b = blockIdx.x;
    const int tid = threadIdx.x;
    const int warp = tid >> 5, lane = tid & 31;

    if (warp == 0) {
        float s0 = g_sc[b*EE + lane];
        float s1 = g_sc[b*EE + lane + 32];
        float s2 = g_sc[b*EE + lane + 64];
        float m = fmaxf(s0, fmaxf(s1, s2));
        #pragma unroll
        for (int off = 16; off > 0; off >>= 1)
            m = fmaxf(m, __shfl_xor_sync(0xffffffffu, m, off));
        float p0 = __expf(s0 - m), p1 = __expf(s1 - m), p2 = __expf(s2 - m);
        float sum = p0 + p1 + p2;
        #pragma unroll
        for (int off = 16; off > 0; off >>= 1)
            sum += __shfl_xor_sync(0xffffffffu, sum, off);
        float inv = 1.0f / sum;
        sc[lane]    = p0 * inv;
        sc[lane+32] = p1 * inv;
        sc[lane+64] = p2 * inv;
    }
    __syncthreads();

    // ws[b][h] = sum_e w_e * enc[b,e,h]  (96 strided L2 loads, deep MLP)
    float acc = 0.0f;
    const float* eb = enc + b*EE*HH + tid;
    #pragma unroll 8
    for (int e = 0; e < EE; e++) acc += sc[e] * eb[e*HH];
    g_ws[b*HH + tid] = acc;
    g_x0[b*KX0 + FF + tid] = acc;
    if (tid < FF) g_x0[b*KX0 + tid] = g_cur[b*FF + tid];
}

// gi0 = x0 @ Wi0^T  (K=544 split {160,128,128,128})
__global__ __launch_bounds__(256) void k_gi0(const float* __restrict__ Wi0) {
    const int k0s[4] = {0, 160, 288, 416};
    const int kls[4] = {160, 128, 128, 128};
    int col0 = blockIdx.x * 64;  // 0..23
    int s = blockIdx.y;
    gemm_tile(g_x0 + k0s[s], KX0,
              Wi0 + col0 * KX0 + k0s[s], KX0,
              g_gi[s] + col0, G3, kls[s]);
}

// gi1 = h0_new @ Wi1^T  (K=512 split 4x128)
__global__ __launch_bounds__(256) void k_gi1(const float* __restrict__ Wi1) {
    int col0 = blockIdx.x * 64;
    int s = blockIdx.y;
    int k0 = s * 128;
    gemm_tile(g_h0 + k0, HH,
              Wi1 + col0 * HH + k0, HH,
              g_gi[s] + col0, G3, 128);
}

// GRU combine: sums K-split partials, applies gates, updates hidden in place
__global__ __launch_bounds__(512) void k_comb(
    const float* __restrict__ bi, const float* __restrict__ bh,
    int ghoff, float* __restrict__ hbuf)
{
    const int b = blockIdx.x;
    const int j = threadIdx.x;
    float ir = bi[j], iz = bi[j+HH], in_ = bi[j+2*HH];
    float hr = bh[j], hz = bh[j+HH], hn  = bh[j+2*HH];
    #pragma unroll
    for (int s = 0; s < 4; s++) {
        const float* gi = g_gi[s] + b*G3;
        ir  += gi[j]; iz += gi[j+HH]; in_ += gi[j+2*HH];
        const float* gh = g_pre[s] + b*NPRE + ghoff;
        hr  += gh[j]; hz += gh[j+HH]; hn  += gh[j+2*HH];
    }
    float r = fast_sigmoid(ir + hr);
    float z = fast_sigmoid(iz + hz);
    float n = fast_tanh(in_ + r * hn);
    float hp = hbuf[b*HH + j];
    hbuf[b*HH + j] = (1.0f - z) * n + z * hp;
}

// output projection + writes d_out + prepares next-step cur
__global__ __launch_bounds__(128) void k_out(
    const float* __restrict__ W_out, const float* __restrict__ b_out,
    const float* __restrict__ inputs, const int* __restrict__ tindices,
    float* __restrict__ dout, int tstep)
{
    const int b = blockIdx.x;
    const int tid = threadIdx.x;   // 128
    const int warp = tid >> 5, lane = tid & 31;
    float a0 = 0.f, a1 = 0.f, a2 = 0.f, a3 = 0.f;
    for (int k = tid; k < KOUT; k += 128) {
        float x;
        if (k < HH)            x = g_h1[b*HH + k];
        else if (k < 2*HH)     x = g_ws[b*HH + k - HH];
        else                   x = g_cur[b*FF + (k - 2*HH)];
        a0 += x * W_out[k];
        a1 += x * W_out[KOUT + k];
        a2 += x * W_out[2*KOUT + k];
        a3 += x * W_out[3*KOUT + k];
    }
    #pragma unroll
    for (int off = 16; off > 0; off >>= 1) {
        a0 += __shfl_xor_sync(0xffffffffu, a0, off);
        a1 += __shfl_xor_sync(0xffffffffu, a1, off);
        a2 += __shfl_xor_sync(0xffffffffu, a2, off);
        a3 += __shfl_xor_sync(0xffffffffu, a3, off);
    }
    __shared__ float red[4][4];
    __shared__ float y[4];
    if (lane == 0) { red[0][warp] = a0; red[1][warp] = a1; red[2][warp] = a2; red[3][warp] = a3; }
    __syncthreads();
    if (tid < 4) {
        float s = red[tid][0] + red[tid][1] + red[tid][2] + red[tid][3] + b_out[tid];
        y[tid] = s;
        dout[(b*DECL + tstep)*TT + tid] = s;
    }
    __syncthreads();
    if (tid < FF) g_cur[b*FF + tid] = inputs[(b*DECL + tstep)*FF + tid];
    __syncthreads();
    if (tid < TT) g_cur[b*FF + tindices[tid]] = y[tid];
}

// ---------------- launch ----------------
extern "C" void kernel_launch(void* const* d_in, const int* in_sizes, int n_in,
                              void* d_out, int out_size)
{
    const float* inputs   = (const float*)d_in[0];
    const float* hidden   = (const float*)d_in[1];
    const float* enc      = (const float*)d_in[2];
    const int*   tindices = (const int*)  d_in[3];
    const float* W_attn   = (const float*)d_in[4];
    const float* b_attn   = (const float*)d_in[5];
    const float* v_attn   = (const float*)d_in[6];
    const float* Wi0      = (const float*)d_in[7];
    const float* Wh0      = (const float*)d_in[8];
    const float* bi0      = (const float*)d_in[9];
    const float* bh0      = (const float*)d_in[10];
    const float* Wi1      = (const float*)d_in[11];
    const float* Wh1      = (const float*)d_in[12];
    const float* bi1      = (const float*)d_in[13];
    const float* bh1      = (const float*)d_in[14];
    const float* W_out    = (const float*)d_in[15];
    const float* b_out    = (const float*)d_in[16];
    float* out = (float*)d_out;

    k_init<<<128, 256>>>(hidden, inputs);
    k_encproj<<<dim3(8, 96), 256>>>(enc, W_attn);

    float* g_h0p; float* g_h1p;
    cudaGetSymbolAddress((void**)&g_h0p, g_h0);
    cudaGetSymbolAddress((void**)&g_h1p, g_h1);

    for (int t = 0; t < DECL; t++) {
        k_pre       <<<dim3(56, 4), 256>>>(W_attn, Wh0, Wh1);
        k_score     <<<BB*6, 512>>>(b_attn, v_attn);
        k_softmax_ws<<<BB, 512>>>(enc);
        k_gi0       <<<dim3(24, 4), 256>>>(Wi0);
        k_comb      <<<64, 512>>>(bi0, bh0, 512,  g_h0p);
        k_gi1       <<<dim3(24, 4), 256>>>(Wi1);
        k_comb      <<<64, 512>>>(bi1, bh1, 2048, g_h1p);
        k_out       <<<64, 128>>>(W_out, b_out, inputs, tindices, out, t);
    }
}

// round 5
// speedup vs baseline: 1.3203x; 1.0128x over previous
#include <cuda_runtime.h>
#include <math.h>

#define BB   64
#define DECL 12
#define FF   32
#define HH   512
#define EE   96
#define TT   4
#define G3   1536
#define NPRE 3584   /* 512 (query) + 1536 (gh0) + 1536 (gh1) */
#define KX0  544    /* F + H */
#define KOUT 1056   /* 2H + F */
#define NBLK 148

// ---------------- device scratch ----------------
__device__ __align__(16) float g_encproj[BB*EE*HH];   // 12.6 MB
__device__ __align__(16) float g_h0[BB*HH];
__device__ __align__(16) float g_h1[BB*HH];
__device__ __align__(16) float g_cur[BB*FF];
__device__ __align__(16) float g_pre[4][BB*NPRE];     // K-split partials: query|gh0|gh1
__device__ __align__(16) float g_gi[8][BB*G3];        // K-split partials for gi
__device__ __align__(16) float g_x0[BB*KX0];          // [cur | ws]
__device__ __align__(16) float g_ws[BB*HH];
__device__ __align__(16) float g_sc[BB*EE];           // attention scores

__device__ unsigned g_bar_cnt = 0;
__device__ unsigned g_bar_gen = 0;

// ---------------- helpers ----------------
__device__ __forceinline__ float fast_sigmoid(float x) {
    return 1.0f / (1.0f + __expf(-x));
}
__device__ __forceinline__ float fast_tanh(float x) {
    float e = __expf(-2.0f * fabsf(x));
    float t = (1.0f - e) / (1.0f + e);
    return copysignf(t, x);
}
__device__ __forceinline__ unsigned long long pack2(float x) {
    unsigned long long r;
    asm("mov.b64 %0, {%1, %1};" : "=l"(r) : "f"(x));
    return r;
}
__device__ __forceinline__ void ffma2(unsigned long long &d, unsigned long long a, unsigned long long b) {
    asm("fma.rn.f32x2 %0, %1, %2, %0;" : "+l"(d) : "l"(a), "l"(b));
}

// software grid barrier (all NBLK blocks resident by construction)
__device__ __forceinline__ void gsync() {
    __syncthreads();
    if (threadIdx.x == 0) {
        __threadfence();
        unsigned gen = *((volatile unsigned*)&g_bar_gen);
        if (atomicAdd(&g_bar_cnt, 1u) == (unsigned)(NBLK - 1)) {
            g_bar_cnt = 0;
            __threadfence();
            *((volatile unsigned*)&g_bar_gen) = gen + 1u;
        } else {
            while (*((volatile unsigned*)&g_bar_gen) == gen) { }
        }
    }
    __syncthreads();
}

// ---------------- shared memory (aliased across phases) ----------------
__shared__ __align__(16) float sAs[64*36];    // 9216 B : GEMM A tile / qs,vs / ho
__shared__ __align__(16) float sWs[32*130];   // 16640 B: GEMM W tile (k-major) / sc / red

// ---------------- f32x2 GEMM tile: C[64][NT] += A[64][klen] @ W[NT][klen]^T ----
// 512 threads. klen % 32 == 0. A/W/C pre-offset. ACG: A via __ldcg (activation).
template<int NT, bool ACG>
__device__ __forceinline__ void gemm_f2(
    const float* __restrict__ A, int lda,
    const float* __restrict__ W, int ldw,
    float* __restrict__ C, int ldc, int klen)
{
    const int tid = threadIdx.x;
    const int ty  = tid >> 5;      // 0..15 row group
    const int txp = tid & 31;      // pair index
    constexpr int NPAIR = NT / 64; // 1 or 2
    constexpr int WST = NT + 2;    // Ws row stride (floats)
    unsigned long long acc[4][NPAIR] = {};

    for (int k0 = 0; k0 < klen; k0 += 32) {
        { // stage A: 64x32 floats = 512 float4 (one per thread), row-major [64][36]
            int row = tid >> 3, q = (tid & 7) << 2;
            const float4* p = reinterpret_cast<const float4*>(&A[row*lda + k0 + q]);
            float4 v = ACG ? __ldcg(p) : __ldg(p);
            *reinterpret_cast<float4*>(&sAs[row*36 + q]) = v;
        }
        // stage W k-major: Ws[kk][col]
        #pragma unroll
        for (int ph = 0; ph < NT/64; ph++) {
            int t2 = tid + ph*512;
            int row = t2 >> 3, q = (t2 & 7) << 2;
            float4 v = __ldg(reinterpret_cast<const float4*>(&W[row*ldw + k0 + q]));
            sWs[(q+0)*WST + row] = v.x;
            sWs[(q+1)*WST + row] = v.y;
            sWs[(q+2)*WST + row] = v.z;
            sWs[(q+3)*WST + row] = v.w;
        }
        __syncthreads();

        #pragma unroll
        for (int kk = 0; kk < 32; kk++) {
            unsigned long long w[NPAIR];
            #pragma unroll
            for (int j = 0; j < NPAIR; j++)
                w[j] = *reinterpret_cast<const unsigned long long*>(&sWs[kk*WST + 2*(txp + 32*j)]);
            #pragma unroll
            for (int i = 0; i < 4; i++) {
                unsigned long long ap = pack2(sAs[(ty + 16*i)*36 + kk]);
                #pragma unroll
                for (int j = 0; j < NPAIR; j++) ffma2(acc[i][j], ap, w[j]);
            }
        }
        __syncthreads();
    }

    #pragma unroll
    for (int i = 0; i < 4; i++)
        #pragma unroll
        for (int j = 0; j < NPAIR; j++) {
            float2 r = *reinterpret_cast<float2*>(&acc[i][j]);
            __stcg(reinterpret_cast<float2*>(&C[(ty + 16*i)*ldc + 2*(txp + 32*j)]), r);
        }
}

// ---------------- the whole decoder in one persistent kernel ----------------
__global__ __launch_bounds__(512, 1) void k_decoder(
    const float* __restrict__ inputs, const float* __restrict__ hidden,
    const float* __restrict__ enc,    const int* __restrict__ tind,
    const float* __restrict__ Wattn,  const float* __restrict__ b_attn,
    const float* __restrict__ v_attn,
    const float* __restrict__ Wi0, const float* __restrict__ Wh0,
    const float* __restrict__ bi0, const float* __restrict__ bh0,
    const float* __restrict__ Wi1, const float* __restrict__ Wh1,
    const float* __restrict__ bi1, const float* __restrict__ bh1,
    const float* __restrict__ W_out, const float* __restrict__ b_out,
    float* __restrict__ dout)
{
    const int bid  = blockIdx.x;
    const int tid  = threadIdx.x;
    const int warp = tid >> 5, lane = tid & 31;

    // ===== phase E: init + enc_proj =====
    for (int i = bid*512 + tid; i < BB*HH; i += NBLK*512) {
        __stcg(&g_h0[i], __ldg(&hidden[i]));
        __stcg(&g_h1[i], __ldg(&hidden[BB*HH + i]));
    }
    for (int i = bid*512 + tid; i < BB*FF; i += NBLK*512) {
        int b = i >> 5, f = i & 31;
        __stcg(&g_cur[i], __ldg(&inputs[b*DECL*FF + f]));
    }
    for (int it = bid; it < 96*4; it += NBLK) {
        __syncthreads();
        int m = it >> 2, n = it & 3;    // M-tile (64 rows of b*E+e), N-tile (128 g)
        gemm_f2<128,false>(enc + m*64*HH, HH,
                           Wattn + n*128*(2*HH) + HH, 2*HH,
                           g_encproj + m*64*HH + n*128, HH, HH);
    }
    gsync();

    // ===== 12 decode steps =====
    for (int t = 0; t < DECL; t++) {
        // --- P1: pre GEMM (query | gh0 | gh1), N=3584 in 28x128 tiles, K split 4x128
        for (int it = bid; it < 112; it += NBLK) {
            __syncthreads();
            int col0 = (it >> 2) * 128;
            int s    = it & 3;
            int k0   = s * 128;
            const float* A; const float* W; int ldw;
            if (col0 < 512)       { A = g_h1; W = Wattn + col0*(2*HH);    ldw = 2*HH; }
            else if (col0 < 2048) { A = g_h0; W = Wh0 + (col0-512)*HH;    ldw = HH; }
            else                  { A = g_h1; W = Wh1 + (col0-2048)*HH;   ldw = HH; }
            gemm_f2<128,true>(A + k0, HH, W + k0, ldw, g_pre[s] + col0, NPRE, 128);
        }
        gsync();

        // --- P2: scores (one warp per (b,e))
        for (int it = bid; it < BB*6; it += NBLK) {
            __syncthreads();
            int b = it / 6, part = it % 6;
            float q = __ldg(&b_attn[tid]);
            #pragma unroll
            for (int s = 0; s < 4; s++) q += __ldcg(&g_pre[s][b*NPRE + tid]);
            sAs[tid] = q;                     // qs
            sAs[512 + tid] = __ldg(&v_attn[tid]);  // vs
            __syncthreads();
            int e = part*16 + warp;
            const float4* ep4 = reinterpret_cast<const float4*>(g_encproj + (b*EE + e)*HH);
            float ssum = 0.0f;
            #pragma unroll
            for (int i = 0; i < 4; i++) {
                float4 v = __ldg(&ep4[i*32 + lane]);
                int g = (i*32 + lane) * 4;
                ssum += fast_tanh(v.x + sAs[g  ]) * sAs[512+g  ];
                ssum += fast_tanh(v.y + sAs[g+1]) * sAs[512+g+1];
                ssum += fast_tanh(v.z + sAs[g+2]) * sAs[512+g+2];
                ssum += fast_tanh(v.w + sAs[g+3]) * sAs[512+g+3];
            }
            #pragma unroll
            for (int off = 16; off > 0; off >>= 1)
                ssum += __shfl_xor_sync(0xffffffffu, ssum, off);
            if (lane == 0) __stcg(&g_sc[b*EE + e], ssum);
        }
        gsync();

        // --- P3: softmax + weighted sum + assemble x0
        for (int it = bid; it < BB; it += NBLK) {
            __syncthreads();
            int b = it;
            if (warp == 0) {
                float s0 = __ldcg(&g_sc[b*EE + lane]);
                float s1 = __ldcg(&g_sc[b*EE + lane + 32]);
                float s2 = __ldcg(&g_sc[b*EE + lane + 64]);
                float m = fmaxf(s0, fmaxf(s1, s2));
                #pragma unroll
                for (int off = 16; off > 0; off >>= 1)
                    m = fmaxf(m, __shfl_xor_sync(0xffffffffu, m, off));
                float p0 = __expf(s0-m), p1 = __expf(s1-m), p2 = __expf(s2-m);
                float sum = p0 + p1 + p2;
                #pragma unroll
                for (int off = 16; off > 0; off >>= 1)
                    sum += __shfl_xor_sync(0xffffffffu, sum, off);
                float inv = 1.0f / sum;
                sWs[lane] = p0*inv; sWs[lane+32] = p1*inv; sWs[lane+64] = p2*inv;
            }
            __syncthreads();
            float acc = 0.0f;
            const float* eb = enc + b*EE*HH + tid;
            #pragma unroll 8
            for (int e = 0; e < EE; e++) acc += sWs[e] * __ldg(&eb[e*HH]);
            __stcg(&g_ws[b*HH + tid], acc);
            __stcg(&g_x0[b*KX0 + FF + tid], acc);
            if (tid < FF) __stcg(&g_x0[b*KX0 + tid], __ldcg(&g_cur[b*FF + tid]));
        }
        gsync();

        // --- P4: gi0 = x0 @ Wi0^T  (12x128 N-tiles, K=544 split 8: 7x64 + 96)
        for (int it = bid; it < 96; it += NBLK) {
            __syncthreads();
            int col0 = (it >> 3) * 128;
            int s    = it & 7;
            int k0   = s * 64;
            int klen = (s == 7) ? 96 : 64;
            gemm_f2<128,true>(g_x0 + k0, KX0, Wi0 + col0*KX0 + k0, KX0,
                              g_gi[s] + col0, G3, klen);
        }
        gsync();

        // --- P5: GRU combine layer 0 -> h0
        for (int it = bid; it < BB; it += NBLK) {
            int b = it, j = tid;
            float ir = __ldg(&bi0[j]), iz = __ldg(&bi0[j+HH]), in_ = __ldg(&bi0[j+2*HH]);
            float hr = __ldg(&bh0[j]), hz = __ldg(&bh0[j+HH]), hn  = __ldg(&bh0[j+2*HH]);
            #pragma unroll
            for (int s = 0; s < 8; s++) {
                const float* gi = g_gi[s] + b*G3;
                ir += __ldcg(&gi[j]); iz += __ldcg(&gi[j+HH]); in_ += __ldcg(&gi[j+2*HH]);
            }
            #pragma unroll
            for (int s = 0; s < 4; s++) {
                const float* gh = g_pre[s] + b*NPRE + 512;
                hr += __ldcg(&gh[j]); hz += __ldcg(&gh[j+HH]); hn += __ldcg(&gh[j+2*HH]);
            }
            float r = fast_sigmoid(ir + hr);
            float z = fast_sigmoid(iz + hz);
            float n = fast_tanh(in_ + r * hn);
            float hp = __ldcg(&g_h0[b*HH + j]);
            __stcg(&g_h0[b*HH + j], (1.0f - z)*n + z*hp);
        }
        gsync();

        // --- P6: gi1 = h0_new @ Wi1^T  (12x128 N-tiles, K=512 split 8x64)
        for (int it = bid; it < 96; it += NBLK) {
            __syncthreads();
            int col0 = (it >> 3) * 128;
            int s    = it & 7;
            int k0   = s * 64;
            gemm_f2<128,true>(g_h0 + k0, HH, Wi1 + col0*HH + k0, HH,
                              g_gi[s] + col0, G3, 64);
        }
        gsync();

        // --- P7: GRU combine layer 1 -> h1, fused output projection + next cur
        for (int it = bid; it < BB; it += NBLK) {
            __syncthreads();
            int b = it, j = tid;
            float ir = __ldg(&bi1[j]), iz = __ldg(&bi1[j+HH]), in_ = __ldg(&bi1[j+2*HH]);
            float hr = __ldg(&bh1[j]), hz = __ldg(&bh1[j+HH]), hn  = __ldg(&bh1[j+2*HH]);
            #pragma unroll
            for (int s = 0; s < 8; s++) {
                const float* gi = g_gi[s] + b*G3;
                ir += __ldcg(&gi[j]); iz += __ldcg(&gi[j+HH]); in_ += __ldcg(&gi[j+2*HH]);
            }
            #pragma unroll
            for (int s = 0; s < 4; s++) {
                const float* gh = g_pre[s] + b*NPRE + 2048;
                hr += __ldcg(&gh[j]); hz += __ldcg(&gh[j+HH]); hn += __ldcg(&gh[j+2*HH]);
            }
            float r = fast_sigmoid(ir + hr);
            float z = fast_sigmoid(iz + hz);
            float n = fast_tanh(in_ + r * hn);
            float hp = __ldcg(&g_h1[b*HH + j]);
            float h1n = (1.0f - z)*n + z*hp;
            __stcg(&g_h1[b*HH + j], h1n);
            sAs[j] = h1n;  // ho
            __syncthreads();

            // out = [h1 | ws | cur] @ W_out^T + b_out
            float a0 = 0.f, a1 = 0.f, a2 = 0.f, a3 = 0.f;
            for (int k = tid; k < KOUT; k += 512) {
                float x;
                if (k < HH)          x = sAs[k];
                else if (k < 2*HH)   x = __ldcg(&g_ws[b*HH + k - HH]);
                else                 x = __ldcg(&g_cur[b*FF + (k - 2*HH)]);
                a0 += x * __ldg(&W_out[k]);
                a1 += x * __ldg(&W_out[KOUT + k]);
                a2 += x * __ldg(&W_out[2*KOUT + k]);
                a3 += x * __ldg(&W_out[3*KOUT + k]);
            }
            #pragma unroll
            for (int off = 16; off > 0; off >>= 1) {
                a0 += __shfl_xor_sync(0xffffffffu, a0, off);
                a1 += __shfl_xor_sync(0xffffffffu, a1, off);
                a2 += __shfl_xor_sync(0xffffffffu, a2, off);
                a3 += __shfl_xor_sync(0xffffffffu, a3, off);
            }
            if (lane == 0) {
                sWs[0*16 + warp] = a0; sWs[16 + warp] = a1;
                sWs[2*16 + warp] = a2; sWs[3*16 + warp] = a3;
            }
            __syncthreads();
            if (tid < 4) {
                float s = b_out[tid];
                #pragma unroll
                for (int w = 0; w < 16; w++) s += sWs[tid*16 + w];
                dout[(b*DECL + t)*TT + tid] = s;
                sWs[64 + tid] = s;
            }
            __syncthreads();
            if (tid < FF)
                __stcg(&g_cur[b*FF + tid], __ldg(&inputs[(b*DECL + t)*FF + tid]));
            __syncthreads();
            if (tid < TT)
                __stcg(&g_cur[b*FF + __ldg(&tind[tid])], sWs[64 + tid]);
        }
        gsync();
    }
}

// ---------------- launch ----------------
extern "C" void kernel_launch(void* const* d_in, const int* in_sizes, int n_in,
                              void* d_out, int out_size)
{
    const float* inputs   = (const float*)d_in[0];
    const float* hidden   = (const float*)d_in[1];
    const float* enc      = (const float*)d_in[2];
    const int*   tindices = (const int*)  d_in[3];
    const float* W_attn   = (const float*)d_in[4];
    const float* b_attn   = (const float*)d_in[5];
    const float* v_attn   = (const float*)d_in[6];
    const float* Wi0      = (const float*)d_in[7];
    const float* Wh0      = (const float*)d_in[8];
    const float* bi0      = (const float*)d_in[9];
    const float* bh0      = (const float*)d_in[10];
    const float* Wi1      = (const float*)d_in[11];
    const float* Wh1      = (const float*)d_in[12];
    const float* bi1      = (const float*)d_in[13];
    const float* bh1      = (const float*)d_in[14];
    const float* W_out    = (const float*)d_in[15];
    const float* b_out    = (const float*)d_in[16];
    float* out = (float*)d_out;

    k_decoder<<<NBLK, 512>>>(inputs, hidden, enc, tindices,
                             W_attn, b_attn, v_attn,
                             Wi0, Wh0, bi0, bh0,
                             Wi1, Wh1, bi1, bh1,
                             W_out, b_out, out);
}